// round 2
// baseline (speedup 1.0000x reference)
#include <cuda_runtime.h>
#include <cuda_bf16.h>
#include <cstddef>

#define N_NODES 512
#define H 8

// ---------------- device scratch ----------------
__device__ __align__(16) float g_qh[N_NODES * H * 60];   // q per head, CG*ATTN_NORM folded
__device__ __align__(16) float g_kh[N_NODES * H * 60];
__device__ __align__(16) float g_A[N_NODES * 9 * 64];    // rec part of W1, per node
__device__ __align__(16) float g_B[N_NODES * 9 * 64];    // snd part of W1, per node
__device__ __align__(16) float g_vmT[480 * N_NODES];     // v transposed: [c][n]
__device__ __align__(16) float g_P[(size_t)N_NODES * N_NODES * H]; // logits+edge_weight

#define CG1 0.5773502691896258f
#define CG2 0.4472135954999579f
#define ATTN_NORM 0.1889822365046136f
#define RS128 0.08838834764831845f
#define RS64  0.125f
#define RS32  0.17677669529663687f

__device__ __forceinline__ float ftanh(float x) {
    // tanh(x) = 1 - 2/(exp(2x)+1); ~1e-6 rel err with MUFU ex2/rcp
    return 1.0f - __fdividef(2.0f, __expf(2.0f * x) + 1.0f);
}

// ================= Kernel 1: per-node precompute =================
__global__ void __launch_bounds__(256) k_node(
    const float* __restrict__ node_feat,
    const float* __restrict__ Wq0, const float* __restrict__ Wq1, const float* __restrict__ Wq2,
    const float* __restrict__ Wk0, const float* __restrict__ Wk1, const float* __restrict__ Wk2,
    const float* __restrict__ Wv0, const float* __restrict__ Wv1, const float* __restrict__ Wv2,
    const float* __restrict__ mW1)
{
    __shared__ float snf[480];
    int n = blockIdx.x;
    for (int i = threadIdx.x; i < 480; i += 256) snf[i] = node_feat[n * 480 + i];
    __syncthreads();

    // q/k/v linears: 3 mats x 480 outputs
    for (int it = threadIdx.x; it < 1440; it += 256) {
        int mat = it / 480, w = it % 480;
        int l, o, m, mul, off;
        if (w < 128)      { l = 0; o = w;            m = 0;           mul = 128; off = 0;   }
        else if (w < 320) { int t = w - 128; l = 1; o = t / 3; m = t % 3; mul = 64; off = 128; }
        else              { int t = w - 320; l = 2; o = t / 5; m = t % 5; mul = 32; off = 320; }
        const float* W;
        if (mat == 0)      W = (l == 0) ? Wq0 : (l == 1) ? Wq1 : Wq2;
        else if (mat == 1) W = (l == 0) ? Wk0 : (l == 1) ? Wk1 : Wk2;
        else               W = (l == 0) ? Wv0 : (l == 1) ? Wv1 : Wv2;
        int d = 2 * l + 1;
        float a0 = 0.f, a1 = 0.f;
        for (int i = 0; i < mul; i += 2) {
            a0 += snf[off + i * d + m]       * W[i * mul + o];
            a1 += snf[off + (i + 1) * d + m] * W[(i + 1) * mul + o];
        }
        float rs = (l == 0) ? RS128 : (l == 1) ? RS64 : RS32;
        float acc = (a0 + a1) * rs;
        if (mat == 2) {
            g_vmT[(size_t)w * N_NODES + n] = acc;   // c == w (same irreps layout)
        } else {
            int am = mul >> 3;
            int hh = o / am, oi = o % am;
            int j = (l == 0) ? oi : (l == 1) ? (16 + oi * 3 + m) : (40 + oi * 5 + m);
            size_t idx = ((size_t)n * H + hh) * 60 + j;
            if (mat == 0) {
                float cg = (l == 0) ? 1.f : (l == 1) ? CG1 : CG2;
                g_qh[idx] = acc * cg * ATTN_NORM;
            } else {
                g_kh[idx] = acc;
            }
        }
    }

    // A/B: 2 x 9 x 64 outputs
    for (int it = threadIdx.x; it < 1152; it += 256) {
        int ab = it / 576, w = it % 576;
        int mp = w / 64, o = w % 64;
        int l, m, mul, off, row;
        if (mp == 0)     { l = 0; m = 0;      mul = 128; off = 0;   row = 32;  }
        else if (mp < 4) { l = 1; m = mp - 1; mul = 64;  off = 128; row = 160; }
        else             { l = 2; m = mp - 4; mul = 32;  off = 320; row = 224; }
        if (ab) row += 224;
        int d = 2 * l + 1;
        float a0 = 0.f, a1 = 0.f;
        for (int i = 0; i < mul; i += 2) {
            a0 += snf[off + i * d + m]       * mW1[(row + i) * 64 + o];
            a1 += snf[off + (i + 1) * d + m] * mW1[(row + i + 1) * 64 + o];
        }
        float cg = (l == 0) ? 1.f : (l == 1) ? CG1 : CG2;
        float acc = (a0 + a1) * cg;
        if (ab) g_B[((size_t)n * 9 + mp) * 64 + o] = acc;
        else    g_A[((size_t)n * 9 + mp) * 64 + o] = acc;
    }
}

// ================= Kernel 2: fused per-edge MLP + logits =================
// smem (float4 units): sQ 1920, sK 1920, sA 2304, sB 2304, sW1 512, sW2 1024,
//                      sW3 128, sb1 16, sb2 16, then 8 floats sb3
#define SMEM2_BYTES ((1920+1920+2304+2304+512+1024+128+16+16)*16 + 8*4)

__global__ void __launch_bounds__(256, 1) k_edge(
    const float* __restrict__ edge_attr, const float* __restrict__ edge_sh,
    const float* __restrict__ mW1, const float* __restrict__ mb1,
    const float* __restrict__ mW2, const float* __restrict__ mb2,
    const float* __restrict__ mW3, const float* __restrict__ mb3)
{
    extern __shared__ float4 sm4[];
    float4* sQ  = sm4;          // [h][j4][r] : h*240 + j4*16 + r
    float4* sK  = sQ  + 1920;   // [h][j4][s]
    float4* sA  = sK  + 1920;   // [m][o4][r] : (m*16+o4)*16 + r
    float4* sB  = sA  + 2304;   // [m][o4][s]
    float4* sW1 = sB  + 2304;   // [e][o4]
    float4* sW2 = sW1 + 512;    // [k][o4]
    float4* sW3 = sW2 + 1024;   // [k][o2]
    float4* sb1 = sW3 + 128;
    float4* sb2 = sb1 + 16;
    float*  sb3 = (float*)(sb2 + 16);

    int tid = threadIdx.x;
    int r0 = blockIdx.y * 16, s0 = blockIdx.x * 16;

    for (int i = tid; i < 1920; i += 256) {
        int hh = i / 240, rem = i % 240, j4 = rem / 16, r = rem % 16;
        sQ[i] = *(const float4*)&g_qh[((size_t)(r0 + r) * H + hh) * 60 + j4 * 4];
        sK[i] = *(const float4*)&g_kh[((size_t)(s0 + r) * H + hh) * 60 + j4 * 4];
    }
    for (int i = tid; i < 2304; i += 256) {
        int m = i / 256, rem = i % 256, o4 = rem / 16, r = rem % 16;
        sA[i] = *(const float4*)&g_A[((size_t)(r0 + r) * 9 + m) * 64 + o4 * 4];
        sB[i] = *(const float4*)&g_B[((size_t)(s0 + r) * 9 + m) * 64 + o4 * 4];
    }
    for (int i = tid; i < 512;  i += 256) sW1[i] = ((const float4*)mW1)[i];
    for (int i = tid; i < 1024; i += 256) sW2[i] = ((const float4*)mW2)[i];
    if (tid < 128) sW3[tid] = ((const float4*)mW3)[tid];
    else if (tid < 144) sb1[tid - 128] = ((const float4*)mb1)[tid - 128];
    else if (tid < 160) sb2[tid - 144] = ((const float4*)mb2)[tid - 144];
    else if (tid < 168) sb3[tid - 160] = mb3[tid - 160];
    __syncthreads();

    int rl = tid >> 4, sl = tid & 15;      // s fastest -> coalesced global loads
    size_t edge = (size_t)(r0 + rl) * N_NODES + (s0 + sl);

    float ea[32];
    {
        const float4* eap = (const float4*)(edge_attr + edge * 32);
#pragma unroll
        for (int e4 = 0; e4 < 8; e4++) {
            float4 v = eap[e4];
            ea[e4*4] = v.x; ea[e4*4+1] = v.y; ea[e4*4+2] = v.z; ea[e4*4+3] = v.w;
        }
    }
    float sh[9];
    {
        const float* shp = edge_sh + edge * 9;
#pragma unroll
        for (int m = 0; m < 9; m++) sh[m] = __ldg(shp + m);
    }

    float h1[64];
#pragma unroll
    for (int o4 = 0; o4 < 16; o4++) {
        float4 b = sb1[o4];
        h1[o4*4] = b.x; h1[o4*4+1] = b.y; h1[o4*4+2] = b.z; h1[o4*4+3] = b.w;
    }
#pragma unroll
    for (int e = 0; e < 32; e++) {
        float c = ea[e];
#pragma unroll
        for (int o4 = 0; o4 < 16; o4++) {
            float4 w = sW1[e * 16 + o4];
            h1[o4*4]   += c * w.x; h1[o4*4+1] += c * w.y;
            h1[o4*4+2] += c * w.z; h1[o4*4+3] += c * w.w;
        }
    }
#pragma unroll
    for (int m = 0; m < 9; m++) {
        float c = sh[m];
#pragma unroll
        for (int o4 = 0; o4 < 16; o4++) {
            float4 w = sA[(m * 16 + o4) * 16 + rl];
            h1[o4*4]   += c * w.x; h1[o4*4+1] += c * w.y;
            h1[o4*4+2] += c * w.z; h1[o4*4+3] += c * w.w;
        }
    }
#pragma unroll
    for (int m = 0; m < 9; m++) {
        float c = sh[m];
#pragma unroll
        for (int o4 = 0; o4 < 16; o4++) {
            float4 w = sB[(m * 16 + o4) * 16 + sl];
            h1[o4*4]   += c * w.x; h1[o4*4+1] += c * w.y;
            h1[o4*4+2] += c * w.z; h1[o4*4+3] += c * w.w;
        }
    }
#pragma unroll
    for (int o = 0; o < 64; o++) h1[o] = ftanh(h1[o]);

    float h2[64];
#pragma unroll
    for (int o4 = 0; o4 < 16; o4++) {
        float4 b = sb2[o4];
        h2[o4*4] = b.x; h2[o4*4+1] = b.y; h2[o4*4+2] = b.z; h2[o4*4+3] = b.w;
    }
#pragma unroll
    for (int k = 0; k < 64; k++) {
        float c = h1[k];
#pragma unroll
        for (int o4 = 0; o4 < 16; o4++) {
            float4 w = sW2[k * 16 + o4];
            h2[o4*4]   += c * w.x; h2[o4*4+1] += c * w.y;
            h2[o4*4+2] += c * w.z; h2[o4*4+3] += c * w.w;
        }
    }
#pragma unroll
    for (int o = 0; o < 64; o++) h2[o] = ftanh(h2[o]);

    float lg[8];
#pragma unroll
    for (int hh = 0; hh < 8; hh++) lg[hh] = sb3[hh];
#pragma unroll
    for (int k = 0; k < 64; k++) {
        float c = h2[k];
        float4 w0 = sW3[k * 2], w1 = sW3[k * 2 + 1];
        lg[0] += c * w0.x; lg[1] += c * w0.y; lg[2] += c * w0.z; lg[3] += c * w0.w;
        lg[4] += c * w1.x; lg[5] += c * w1.y; lg[6] += c * w1.z; lg[7] += c * w1.w;
    }
#pragma unroll
    for (int hh = 0; hh < 8; hh++) {
#pragma unroll
        for (int j4 = 0; j4 < 15; j4++) {
            float4 q = sQ[(hh * 15 + j4) * 16 + rl];
            float4 k = sK[(hh * 15 + j4) * 16 + sl];
            lg[hh] += q.x * k.x + q.y * k.y + q.z * k.z + q.w * k.w;
        }
    }
    float4* Pp = (float4*)(g_P + edge * 8);
    Pp[0] = make_float4(lg[0], lg[1], lg[2], lg[3]);
    Pp[1] = make_float4(lg[4], lg[5], lg[6], lg[7]);
}

// ================= Kernel 3: softmax over senders + aggregation + residual =================
#define SW_STRIDE 520
#define SMEM3_BYTES (4 * 8 * SW_STRIDE * 4)

__device__ __forceinline__ int h_of(int c) {
    if (c < 128) return c >> 4;
    if (c < 320) return ((c - 128) / 3) >> 3;
    return ((c - 320) / 5) >> 2;
}

__global__ void __launch_bounds__(256) k_out(
    const float* __restrict__ node_feat, float* __restrict__ out)
{
    extern __shared__ float sw[];  // [4][8][520]
    int tid = threadIdx.x;
    int r0 = blockIdx.x * 4;

    // load P[r0..r0+3][s][h] into sw[rr][h][s]
    const float4* Psrc = (const float4*)(g_P + (size_t)r0 * N_NODES * H);
    for (int i = tid; i < 4096; i += 256) {
        float4 v = Psrc[i];
        int lin = i * 4;
        int rr = lin >> 12, rem = lin & 4095;
        int s = rem >> 3, hh = rem & 7;
        float* dst = &sw[((rr * 8 + hh) * SW_STRIDE) + s];
        dst[0]           = v.x;
        dst[SW_STRIDE]   = v.y;
        dst[2*SW_STRIDE] = v.z;
        dst[3*SW_STRIDE] = v.w;
    }
    __syncthreads();

    int wid = tid >> 5, lane = tid & 31;
    // softmax over s for each (rr,h)
    for (int p = wid; p < 32; p += 8) {
        float* row = &sw[p * SW_STRIDE];
        float mx = -1e30f;
#pragma unroll
        for (int k = 0; k < 16; k++) mx = fmaxf(mx, row[lane + 32 * k]);
#pragma unroll
        for (int off = 16; off; off >>= 1) mx = fmaxf(mx, __shfl_xor_sync(0xffffffffu, mx, off));
        float sum = 0.f;
#pragma unroll
        for (int k = 0; k < 16; k++) sum += __expf(row[lane + 32 * k] - mx);
#pragma unroll
        for (int off = 16; off; off >>= 1) sum += __shfl_xor_sync(0xffffffffu, sum, off);
        float rinv = __fdividef(1.0f, sum);
#pragma unroll
        for (int k = 0; k < 16; k++) {
            int s = lane + 32 * k;
            row[s] = __expf(row[s] - mx) * rinv;
        }
    }
    __syncthreads();

    // out[r, c] = nf[r, c] + sum_s w[r][h(c)][s] * vmT[c][s]
    for (int c = wid; c < 480; c += 8) {
        int hh = h_of(c);
        const float* vrow = &g_vmT[(size_t)c * N_NODES];
        const float* w0 = &sw[(0 * 8 + hh) * SW_STRIDE];
        const float* w1 = &sw[(1 * 8 + hh) * SW_STRIDE];
        const float* w2 = &sw[(2 * 8 + hh) * SW_STRIDE];
        const float* w3 = &sw[(3 * 8 + hh) * SW_STRIDE];
        float a0 = 0.f, a1 = 0.f, a2 = 0.f, a3 = 0.f;
#pragma unroll
        for (int k = 0; k < 16; k++) {
            int s = k * 32 + lane;
            float vv = vrow[s];
            a0 += w0[s] * vv; a1 += w1[s] * vv; a2 += w2[s] * vv; a3 += w3[s] * vv;
        }
#pragma unroll
        for (int off = 16; off; off >>= 1) {
            a0 += __shfl_xor_sync(0xffffffffu, a0, off);
            a1 += __shfl_xor_sync(0xffffffffu, a1, off);
            a2 += __shfl_xor_sync(0xffffffffu, a2, off);
            a3 += __shfl_xor_sync(0xffffffffu, a3, off);
        }
        if (lane == 0) {
            out[(size_t)(r0 + 0) * 480 + c] = node_feat[(size_t)(r0 + 0) * 480 + c] + a0;
            out[(size_t)(r0 + 1) * 480 + c] = node_feat[(size_t)(r0 + 1) * 480 + c] + a1;
            out[(size_t)(r0 + 2) * 480 + c] = node_feat[(size_t)(r0 + 2) * 480 + c] + a2;
            out[(size_t)(r0 + 3) * 480 + c] = node_feat[(size_t)(r0 + 3) * 480 + c] + a3;
        }
    }
}

// ================= launch =================
extern "C" void kernel_launch(void* const* d_in, const int* in_sizes, int n_in,
                              void* d_out, int out_size)
{
    const float* node_feat = (const float*)d_in[0];
    const float* edge_attr = (const float*)d_in[1];
    const float* edge_sh   = (const float*)d_in[2];
    const float* Wq0 = (const float*)d_in[3];
    const float* Wq1 = (const float*)d_in[4];
    const float* Wq2 = (const float*)d_in[5];
    const float* Wk0 = (const float*)d_in[6];
    const float* Wk1 = (const float*)d_in[7];
    const float* Wk2 = (const float*)d_in[8];
    const float* Wv0 = (const float*)d_in[9];
    const float* Wv1 = (const float*)d_in[10];
    const float* Wv2 = (const float*)d_in[11];
    const float* mW1 = (const float*)d_in[12];
    const float* mb1 = (const float*)d_in[13];
    const float* mW2 = (const float*)d_in[14];
    const float* mb2 = (const float*)d_in[15];
    const float* mW3 = (const float*)d_in[16];
    const float* mb3 = (const float*)d_in[17];
    float* out = (float*)d_out;

    cudaFuncSetAttribute(k_edge, cudaFuncAttributeMaxDynamicSharedMemorySize, SMEM2_BYTES);
    cudaFuncSetAttribute(k_out,  cudaFuncAttributeMaxDynamicSharedMemorySize, SMEM3_BYTES);

    k_node<<<N_NODES, 256>>>(node_feat, Wq0, Wq1, Wq2, Wk0, Wk1, Wk2, Wv0, Wv1, Wv2, mW1);
    dim3 g2(32, 32);
    k_edge<<<g2, 256, SMEM2_BYTES>>>(edge_attr, edge_sh, mW1, mb1, mW2, mb2, mW3, mb3);
    k_out<<<128, 256, SMEM3_BYTES>>>(node_feat, out);
}